// round 16
// baseline (speedup 1.0000x reference)
#include <cuda_runtime.h>
#include <cuda_bf16.h>
#include <stdint.h>

#define DEVI __device__ __forceinline__

namespace {
constexpr int Bb = 4;
constexpr int Tt = 4096;
constexpr int Cc = 1024;
constexpr int Dd = 128;
constexpr int Mm = Bb * Tt;   // 16384
// 1/sqrt(128) * log2(e): S lands in log2 domain, exp = ex2.approx
constexpr float SCALE_L2E = 0.12751741404109246f;
constexpr int QT = 64;
constexpr int NQT = Tt / QT;
constexpr int CHUNK = 512;
constexpr int MAXCH = 8;
constexpr int CTAS_PER_B = 288;   // sum over groups g=0..7: 8 tiles * (g+1) chunks
constexpr int QKV_TILES = 768;    // 3 sels * 256 m-tiles
constexpr int QKV_GRID  = 592;    // persistent CTAs
}

// ---------------- scratch (device globals) -----------------------------------
__device__ __align__(16) __nv_bfloat16 g_xhi[Mm * Cc];
__device__ __align__(16) __nv_bfloat16 g_xlo[Mm * Cc];
__device__ __align__(16) __nv_bfloat16 g_whi[3 * Cc * Dd];   // [sel][k][n]
__device__ __align__(16) __nv_bfloat16 g_wlo[3 * Cc * Dd];
__device__ __align__(16) __nv_bfloat16 g_qhi[Mm * Dd];
__device__ __align__(16) __nv_bfloat16 g_qlo[Mm * Dd];
__device__ __align__(16) __nv_bfloat16 g_khi[Mm * Dd];
__device__ __align__(16) __nv_bfloat16 g_klo[Mm * Dd];
__device__ __align__(16) __nv_bfloat16 g_vhi[Mm * Dd];
__device__ __align__(16) __nv_bfloat16 g_vlo[Mm * Dd];
__device__ __align__(16) float g_po[Bb * NQT * MAXCH * QT * Dd];  // 67 MB
__device__ float g_pl[Bb * NQT * MAXCH * QT];
__device__ unsigned int g_qkv_ctr;

// ---------------- helpers -----------------------------------------------------
DEVI uint32_t su32(const void* p) { return (uint32_t)__cvta_generic_to_shared(p); }

DEVI void ldm4(uint32_t r[4], uint32_t a) {
    asm volatile("ldmatrix.sync.aligned.m8n8.x4.shared.b16 {%0,%1,%2,%3}, [%4];"
                 : "=r"(r[0]), "=r"(r[1]), "=r"(r[2]), "=r"(r[3]) : "r"(a));
}
DEVI void ldm4t(uint32_t r[4], uint32_t a) {
    asm volatile("ldmatrix.sync.aligned.m8n8.x4.trans.shared.b16 {%0,%1,%2,%3}, [%4];"
                 : "=r"(r[0]), "=r"(r[1]), "=r"(r[2]), "=r"(r[3]) : "r"(a));
}
DEVI void mma16816(float c[4], const uint32_t a[4], uint32_t b0, uint32_t b1) {
    asm volatile(
        "mma.sync.aligned.m16n8k16.row.col.f32.bf16.bf16.f32 "
        "{%0,%1,%2,%3}, {%4,%5,%6,%7}, {%8,%9}, {%0,%1,%2,%3};"
        : "+f"(c[0]), "+f"(c[1]), "+f"(c[2]), "+f"(c[3])
        : "r"(a[0]), "r"(a[1]), "r"(a[2]), "r"(a[3]), "r"(b0), "r"(b1));
}
DEVI void cpa16(uint32_t s, const void* g) {
    asm volatile("cp.async.cg.shared.global [%0], [%1], 16;" :: "r"(s), "l"(g));
}
DEVI void cpa8(uint32_t s, const void* g) {
    asm volatile("cp.async.ca.shared.global [%0], [%1], 8;" :: "r"(s), "l"(g));
}
DEVI void cpa_commit() { asm volatile("cp.async.commit_group;"); }
template<int N> DEVI void cpa_wait() { asm volatile("cp.async.wait_group %0;" :: "n"(N)); }

// guaranteed MUFU.EX2
DEVI float ex2(float x) {
    float r;
    asm("ex2.approx.ftz.f32 %0, %1;" : "=f"(r) : "f"(x));
    return r;
}

DEVI uint32_t pack2(__nv_bfloat16 a, __nv_bfloat16 b) {
    __nv_bfloat162 t = __halves2bfloat162(a, b);
    return reinterpret_cast<uint32_t&>(t);
}
DEVI void split2(float a, float b, uint32_t& hi, uint32_t& lo) {
    __nv_bfloat16 ha = __float2bfloat16(a);
    __nv_bfloat16 hb = __float2bfloat16(b);
    hi = pack2(ha, hb);
    lo = pack2(__float2bfloat16(a - __bfloat162float(ha)),
               __float2bfloat16(b - __bfloat162float(hb)));
}

// ---------------- conversion kernels ------------------------------------------
__global__ __launch_bounds__(256) void conv_x_kernel(const float* __restrict__ x) {
    int i = blockIdx.x * 256 + threadIdx.x;
    float4 v = reinterpret_cast<const float4*>(x)[i];
    uint32_t h0, l0, h1, l1;
    split2(v.x, v.y, h0, l0);
    split2(v.z, v.w, h1, l1);
    reinterpret_cast<uint2*>(g_xhi)[i] = make_uint2(h0, h1);
    reinterpret_cast<uint2*>(g_xlo)[i] = make_uint2(l0, l1);
}

__global__ __launch_bounds__(256) void conv_w_kernel(
    const float* __restrict__ Wq, const float* __restrict__ Wk, const float* __restrict__ Wv) {
    if (blockIdx.x == 0 && blockIdx.y == 0 && threadIdx.x == 0)
        g_qkv_ctr = QKV_GRID;    // reset work-stealing counter (stream-ordered)
    int sel = blockIdx.y;
    const float* W = (sel == 0) ? Wq : (sel == 1 ? Wk : Wv);
    int i = blockIdx.x * 256 + threadIdx.x;
    float4 v = reinterpret_cast<const float4*>(W)[i];
    uint32_t h0, l0, h1, l1;
    split2(v.x, v.y, h0, l0);
    split2(v.z, v.w, h1, l1);
    reinterpret_cast<uint2*>(g_whi)[sel * 32768 + i] = make_uint2(h0, h1);
    reinterpret_cast<uint2*>(g_wlo)[sel * 32768 + i] = make_uint2(l0, l1);
}

// ---------------- kernel 1: QKV GEMM (BM=64, 128 thr, persistent + stealing) ----
namespace qk {
constexpr int A_HI = 0;          // 64 rows * 80B = 5120
constexpr int A_LO = 5120;
constexpr int B_HI = 10240;      // 32 rows * 272B = 8704
constexpr int B_LO = 18944;
constexpr int STG  = 27648;
constexpr int NEXT = STG * 2;    // 4-byte broadcast slot for stolen tile id
constexpr int SMEM = STG * 2 + 16;
}

__global__ __launch_bounds__(128) void qkv_kernel() {
    extern __shared__ char dsm[];
    const uint32_t sb0 = su32(dsm);

    const int tid  = threadIdx.x;
    const int warp = tid >> 5;
    const int lane = tid & 31;
    const int wm = warp & 1;
    const int wn = warp >> 1;
    const int g  = lane >> 2;
    const int tg = lane & 3;

    int u = blockIdx.x;   // tile id: sel = u>>8, m-tile = u&255

    while (u < QKV_TILES) {
        const int sel = u >> 8;
        const int m0  = (u & 255) * 64;
        __nv_bfloat16* Ohi = (sel == 0) ? g_qhi : (sel == 1 ? g_khi : g_vhi);
        __nv_bfloat16* Olo = (sel == 0) ? g_qlo : (sel == 1 ? g_klo : g_vlo);

        auto load_stage = [&](int st, int k0) {
            uint32_t sb = sb0 + st * qk::STG;
#pragma unroll
            for (int i = 0; i < 4; i++) {
                int idx = tid + i * 128;          // 0..511
                int r = idx >> 3, c = idx & 7;
                uint32_t so = r * 80 + c * 8;
                size_t ge = (size_t)(m0 + r) * Cc + k0 + c * 4;
                cpa8(sb + qk::A_HI + so, (const char*)g_xhi + ge * 2);
                cpa8(sb + qk::A_LO + so, (const char*)g_xlo + ge * 2);
            }
#pragma unroll
            for (int i = 0; i < 4; i++) {
                int idx = tid + i * 128;          // 0..511
                int r = idx >> 4, c = idx & 15;
                uint32_t so = r * 272 + c * 16;
                size_t ge = (size_t)sel * Cc * Dd + (size_t)(k0 + r) * Dd + c * 8;
                cpa16(sb + qk::B_HI + so, (const char*)g_whi + ge * 2);
                cpa16(sb + qk::B_LO + so, (const char*)g_wlo + ge * 2);
            }
            cpa_commit();
        };

        constexpr int NT = Cc / 32;
        load_stage(0, 0);
        load_stage(1, 32);

        float acc[2][8][4] = {};

        for (int t = 0; t < NT; t++) {
            if (t + 1 < NT) cpa_wait<1>(); else cpa_wait<0>();
            __syncthreads();

            uint32_t sb = sb0 + (t & 1) * qk::STG;
#pragma unroll
            for (int ks = 0; ks < 2; ks++) {
                uint32_t ah[2][4], al[2][4];
#pragma unroll
                for (int mi = 0; mi < 2; mi++) {
                    int arow = wm * 32 + mi * 16 + (lane & 15);
                    int acol = ks * 16 + (lane >> 4) * 8;
                    ldm4(ah[mi], sb + qk::A_HI + arow * 80 + acol * 2);
                    ldm4(al[mi], sb + qk::A_LO + arow * 80 + acol * 2);
                }
#pragma unroll
                for (int nb = 0; nb < 4; nb++) {
                    uint32_t bh[4], bl[4];
                    int brow = ks * 16 + (lane & 7) + ((lane >> 3) & 1) * 8;
                    int bcol = wn * 64 + nb * 16 + (lane >> 4) * 8;
                    ldm4t(bh, sb + qk::B_HI + brow * 272 + bcol * 2);
                    ldm4t(bl, sb + qk::B_LO + brow * 272 + bcol * 2);
#pragma unroll
                    for (int sub = 0; sub < 2; sub++) {
#pragma unroll
                        for (int mi = 0; mi < 2; mi++) {
                            float* cc = acc[mi][nb * 2 + sub];
                            mma16816(cc, ah[mi], bh[2 * sub], bh[2 * sub + 1]);
                            mma16816(cc, ah[mi], bl[2 * sub], bl[2 * sub + 1]);
                            mma16816(cc, al[mi], bh[2 * sub], bh[2 * sub + 1]);
                        }
                    }
                }
            }
            __syncthreads();
            if (t + 2 < NT) load_stage(t & 1, (t + 2) * 32);
        }

        const float sc = (sel == 0) ? SCALE_L2E : 1.0f;
#pragma unroll
        for (int mi = 0; mi < 2; mi++) {
            int r0 = m0 + wm * 32 + mi * 16 + g;
#pragma unroll
            for (int nj = 0; nj < 8; nj++) {
                int col = wn * 64 + nj * 8 + 2 * tg;
                uint32_t hi, lo;
                split2(acc[mi][nj][0] * sc, acc[mi][nj][1] * sc, hi, lo);
                *reinterpret_cast<uint32_t*>(&Ohi[(size_t)r0 * Dd + col]) = hi;
                *reinterpret_cast<uint32_t*>(&Olo[(size_t)r0 * Dd + col]) = lo;
                split2(acc[mi][nj][2] * sc, acc[mi][nj][3] * sc, hi, lo);
                *reinterpret_cast<uint32_t*>(&Ohi[(size_t)(r0 + 8) * Dd + col]) = hi;
                *reinterpret_cast<uint32_t*>(&Olo[(size_t)(r0 + 8) * Dd + col]) = lo;
            }
        }

        if (tid == 0) {
            unsigned int nx = atomicAdd(&g_qkv_ctr, 1u);
            *reinterpret_cast<uint32_t*>(dsm + qk::NEXT) = nx;
        }
        __syncthreads();
        u = (int)*reinterpret_cast<uint32_t*>(dsm + qk::NEXT);
    }
}

// ---------------- kernel 2: split-KV causal attention, fixed-base softmax ------
namespace at {
constexpr int K_HI = 0;          // 32 rows * 272B = 8704 each
constexpr int K_LO = 8704;
constexpr int V_HI = 17408;
constexpr int V_LO = 26112;
constexpr int STG  = 34816;
constexpr int SMEM = STG * 2;    // 69632 (x3 CTAs = 209 KB < 228 KB)
}

// force 3 CTAs/SM: caps regs at 170 (round-12 body fit in 168)
__global__ __launch_bounds__(128, 3) void attn_kernel()
{
    extern __shared__ char dsm[];
    const uint32_t sb0 = su32(dsm);

    // longest-first over CHUNK=512 chunks.
    // group boundaries at 4g(g+1); inverse: grp = (sqrt(c+1)-1)/2
    // (round-14 bug: used sqrt(4c+1)). Clamp loops guarantee range.
    const int c = CTAS_PER_B - 1 - blockIdx.x;
    int grp = (int)((sqrtf((float)(c + 1)) - 1.0f) * 0.5f);
    while (grp > 0 && 4 * grp * (grp + 1) > c) grp--;
    while (4 * (grp + 1) * (grp + 2) <= c) grp++;
    const int idx = c - 4 * grp * (grp + 1);
    const int itile = grp * 8 + idx / (grp + 1);
    const int ch    = idx % (grp + 1);

    const int bidx  = blockIdx.y;
    const int q0    = itile * QT;
    const int s_beg = ch * CHUNK;
    const int q_end = q0 + QT;
    const int s_end = (s_beg + CHUNK < q_end) ? (s_beg + CHUNK) : q_end;
    const int nt    = (s_end - s_beg) >> 5;

    const int tid  = threadIdx.x;
    const int warp = tid >> 5;
    const int lane = tid & 31;
    const int g  = lane >> 2;
    const int tg = lane & 3;
    const int wq = warp * 16;

    auto load_tile = [&](int st, int s0) {
        uint32_t sb = sb0 + st * at::STG;
        size_t gbyte = ((size_t)bidx * Tt + s0) * Dd * 2;
        const char* kh = (const char*)g_khi + gbyte;
        const char* kl = (const char*)g_klo + gbyte;
        const char* vh = (const char*)g_vhi + gbyte;
        const char* vl = (const char*)g_vlo + gbyte;
#pragma unroll
        for (int i = 0; i < 4; i++) {
            int idx2 = tid + i * 128;
            int r = idx2 >> 4, cc = idx2 & 15;
            uint32_t so = r * 272 + cc * 16;
            size_t go = (size_t)idx2 * 16;
            cpa16(sb + at::K_HI + so, kh + go);
            cpa16(sb + at::K_LO + so, kl + go);
            cpa16(sb + at::V_HI + so, vh + go);
            cpa16(sb + at::V_LO + so, vl + go);
        }
        cpa_commit();
    };

    uint32_t qh[8][4], ql[8][4];
    {
        size_t bt = ((size_t)bidx * Tt + q0 + wq + g) * Dd;
#pragma unroll
        for (int kt = 0; kt < 8; kt++) {
            int c0 = kt * 16 + 2 * tg;
            qh[kt][0] = *reinterpret_cast<const uint32_t*>(&g_qhi[bt + c0]);
            qh[kt][1] = *reinterpret_cast<const uint32_t*>(&g_qhi[bt + 8 * Dd + c0]);
            qh[kt][2] = *reinterpret_cast<const uint32_t*>(&g_qhi[bt + c0 + 8]);
            qh[kt][3] = *reinterpret_cast<const uint32_t*>(&g_qhi[bt + 8 * Dd + c0 + 8]);
            ql[kt][0] = *reinterpret_cast<const uint32_t*>(&g_qlo[bt + c0]);
            ql[kt][1] = *reinterpret_cast<const uint32_t*>(&g_qlo[bt + 8 * Dd + c0]);
            ql[kt][2] = *reinterpret_cast<const uint32_t*>(&g_qlo[bt + c0 + 8]);
            ql[kt][3] = *reinterpret_cast<const uint32_t*>(&g_qlo[bt + 8 * Dd + c0 + 8]);
        }
    }

    float oacc[16][4] = {};
    float l_t = 0.f, l_b = 0.f;

    load_tile(0, s_beg);
    if (nt > 1) load_tile(1, s_beg + 32);

    for (int t = 0; t < nt; t++) {
        if (t + 1 < nt) cpa_wait<1>(); else cpa_wait<0>();
        __syncthreads();

        const uint32_t sb = sb0 + (t & 1) * at::STG;
        const int s0 = s_beg + t * 32;

        float sacc[4][4] = {};
#pragma unroll
        for (int kt = 0; kt < 8; kt++) {
#pragma unroll
            for (int np = 0; np < 2; np++) {
                uint32_t kh[4], kl[4];
                int srow = np * 16 + ((lane >> 4) << 3) + (lane & 7);
                int kcol = kt * 16 + ((lane >> 3) & 1) * 8;
                ldm4(kh, sb + at::K_HI + srow * 272 + kcol * 2);
                ldm4(kl, sb + at::K_LO + srow * 272 + kcol * 2);
#pragma unroll
                for (int sub = 0; sub < 2; sub++) {
                    float* cc = sacc[np * 2 + sub];
                    mma16816(cc, qh[kt], kh[2 * sub], kh[2 * sub + 1]);
                    mma16816(cc, qh[kt], kl[2 * sub], kl[2 * sub + 1]);
                    mma16816(cc, ql[kt], kh[2 * sub], kh[2 * sub + 1]);
                }
            }
        }

        const int rt = q0 + wq + g;
        if (s0 + 31 > q0 + wq) {
#pragma unroll
            for (int nj = 0; nj < 4; nj++) {
                int cgl = s0 + nj * 8 + 2 * tg;
                if (cgl     > rt)     sacc[nj][0] = -1e30f;
                if (cgl + 1 > rt)     sacc[nj][1] = -1e30f;
                if (cgl     > rt + 8) sacc[nj][2] = -1e30f;
                if (cgl + 1 > rt + 8) sacc[nj][3] = -1e30f;
            }
        }

        // fixed-base softmax: P = 2^S (masked -> 0); accumulate l per thread
#pragma unroll
        for (int nj = 0; nj < 4; nj++) {
            sacc[nj][0] = ex2(sacc[nj][0]);
            sacc[nj][1] = ex2(sacc[nj][1]);
            sacc[nj][2] = ex2(sacc[nj][2]);
            sacc[nj][3] = ex2(sacc[nj][3]);
            l_t += sacc[nj][0] + sacc[nj][1];
            l_b += sacc[nj][2] + sacc[nj][3];
        }

        uint32_t ph[2][4], pl[2][4];
#pragma unroll
        for (int kb = 0; kb < 2; kb++) {
            split2(sacc[kb * 2][0],     sacc[kb * 2][1],     ph[kb][0], pl[kb][0]);
            split2(sacc[kb * 2][2],     sacc[kb * 2][3],     ph[kb][1], pl[kb][1]);
            split2(sacc[kb * 2 + 1][0], sacc[kb * 2 + 1][1], ph[kb][2], pl[kb][2]);
            split2(sacc[kb * 2 + 1][2], sacc[kb * 2 + 1][3], ph[kb][3], pl[kb][3]);
        }
#pragma unroll
        for (int kb = 0; kb < 2; kb++) {
            int vrow = kb * 16 + (lane & 7) + ((lane >> 3) & 1) * 8;
#pragma unroll
            for (int db = 0; db < 8; db++) {
                uint32_t vh[4], vl[4];
                int vcol = db * 16 + (lane >> 4) * 8;
                ldm4t(vh, sb + at::V_HI + vrow * 272 + vcol * 2);
                ldm4t(vl, sb + at::V_LO + vrow * 272 + vcol * 2);
#pragma unroll
                for (int sub = 0; sub < 2; sub++) {
                    float* cc = oacc[db * 2 + sub];
                    mma16816(cc, ph[kb], vh[2 * sub], vh[2 * sub + 1]);
                    mma16816(cc, pl[kb], vh[2 * sub], vh[2 * sub + 1]);
                    mma16816(cc, ph[kb], vl[2 * sub], vl[2 * sub + 1]);
                }
            }
        }

        __syncthreads();
        if (t + 2 < nt) load_tile(t & 1, s_beg + (t + 2) * 32);
    }

    l_t += __shfl_xor_sync(0xffffffffu, l_t, 1);
    l_t += __shfl_xor_sync(0xffffffffu, l_t, 2);
    l_b += __shfl_xor_sync(0xffffffffu, l_b, 1);
    l_b += __shfl_xor_sync(0xffffffffu, l_b, 2);

    const int part  = ((bidx * NQT + itile) * MAXCH + ch);
    const int row_t = wq + g;
    float* po = &g_po[(size_t)part * QT * Dd];
    if (tg == 0) {
        g_pl[part * QT + row_t]     = l_t;
        g_pl[part * QT + row_t + 8] = l_b;
    }
#pragma unroll
    for (int d = 0; d < 16; d++) {
        int col = d * 8 + 2 * tg;
        *reinterpret_cast<float2*>(&po[row_t * Dd + col])       = make_float2(oacc[d][0], oacc[d][1]);
        *reinterpret_cast<float2*>(&po[(row_t + 8) * Dd + col]) = make_float2(oacc[d][2], oacc[d][3]);
    }
}

// ---------------- kernel 3: combine (plain sum; shared base) --------------------
__global__ __launch_bounds__(128) void combine_kernel(float* __restrict__ out)
{
    const int warp = threadIdx.x >> 5;
    const int lane = threadIdx.x & 31;
    const int r = blockIdx.x * 4 + warp;
    const int b = r >> 12;
    const int rem = r & 4095;
    const int i = rem >> 6;
    const int row_in = rem & 63;
    const int nch = (i >> 3) + 1;     // CHUNK=512: group = i>>3

    const int pbase = ((b * NQT + i) * MAXCH);

    float4 acc = make_float4(0.f, 0.f, 0.f, 0.f);
    float lsum = 0.f;
#pragma unroll
    for (int cch = 0; cch < MAXCH; cch++) {
        if (cch >= nch) break;
        lsum += g_pl[(pbase + cch) * QT + row_in];
        float4 v = *reinterpret_cast<const float4*>(
            &g_po[((size_t)(pbase + cch) * QT + row_in) * Dd + lane * 4]);
        acc.x += v.x; acc.y += v.y; acc.z += v.z; acc.w += v.w;
    }
    float inv = 1.f / lsum;
    float4 o = make_float4(acc.x * inv, acc.y * inv, acc.z * inv, acc.w * inv);
    *reinterpret_cast<float4*>(&out[((size_t)b * Tt + i * QT + row_in) * Dd + lane * 4]) = o;
}

// ---------------- launcher --------------------------------------------------------
extern "C" void kernel_launch(void* const* d_in, const int* in_sizes, int n_in,
                              void* d_out, int out_size) {
    const float* x  = (const float*)d_in[0];
    const float* Wq = (const float*)d_in[1];
    const float* Wk = (const float*)d_in[2];
    const float* Wv = (const float*)d_in[3];
    float* out = (float*)d_out;

    cudaFuncSetAttribute(qkv_kernel, cudaFuncAttributeMaxDynamicSharedMemorySize, qk::SMEM);
    cudaFuncSetAttribute(attn_kernel, cudaFuncAttributeMaxDynamicSharedMemorySize, at::SMEM);

    conv_x_kernel<<<(Mm * Cc / 4) / 256, 256>>>(x);
    conv_w_kernel<<<dim3((Cc * Dd / 4) / 256, 3), 256>>>(Wq, Wk, Wv);
    qkv_kernel<<<QKV_GRID, 128, qk::SMEM>>>();
    attn_kernel<<<dim3(CTAS_PER_B, Bb), 128, at::SMEM>>>();
    combine_kernel<<<Mm / 4, 128>>>(out);
}

// round 17
// speedup vs baseline: 1.0376x; 1.0376x over previous
#include <cuda_runtime.h>
#include <cuda_bf16.h>
#include <stdint.h>

#define DEVI __device__ __forceinline__

namespace {
constexpr int Bb = 4;
constexpr int Tt = 4096;
constexpr int Cc = 1024;
constexpr int Dd = 128;
constexpr int Mm = Bb * Tt;   // 16384
// 1/sqrt(128) * log2(e): S lands in log2 domain, exp = ex2.approx
constexpr float SCALE_L2E = 0.12751741404109246f;
constexpr int QT = 64;
constexpr int NQT = Tt / QT;
constexpr int CHUNK = 512;
constexpr int MAXCH = 8;
constexpr int CTAS_PER_B = 288;   // groups g=0..7: 8 tiles * (g+1) chunks
constexpr int QKV_TILES = 768;    // 3 sels * 256 m-tiles
constexpr int QKV_GRID  = 592;    // persistent CTAs
}

// ---------------- scratch (device globals) -----------------------------------
__device__ __align__(16) __nv_bfloat16 g_xhi[Mm * Cc];
__device__ __align__(16) __nv_bfloat16 g_xlo[Mm * Cc];
__device__ __align__(16) __nv_bfloat16 g_whi[3 * Cc * Dd];   // [sel][k][n]
__device__ __align__(16) __nv_bfloat16 g_wlo[3 * Cc * Dd];
__device__ __align__(16) __nv_bfloat16 g_qhi[Mm * Dd];
__device__ __align__(16) __nv_bfloat16 g_qlo[Mm * Dd];
__device__ __align__(16) __nv_bfloat16 g_khi[Mm * Dd];
__device__ __align__(16) __nv_bfloat16 g_klo[Mm * Dd];
__device__ __align__(16) __nv_bfloat16 g_vhi[Mm * Dd];
__device__ __align__(16) __nv_bfloat16 g_vlo[Mm * Dd];
__device__ __align__(16) float g_po[Bb * NQT * MAXCH * QT * Dd];  // 67 MB
__device__ float g_pl[Bb * NQT * MAXCH * QT];
__device__ unsigned int g_qkv_ctr;

// ---------------- helpers -----------------------------------------------------
DEVI uint32_t su32(const void* p) { return (uint32_t)__cvta_generic_to_shared(p); }

DEVI void ldm4(uint32_t r[4], uint32_t a) {
    asm volatile("ldmatrix.sync.aligned.m8n8.x4.shared.b16 {%0,%1,%2,%3}, [%4];"
                 : "=r"(r[0]), "=r"(r[1]), "=r"(r[2]), "=r"(r[3]) : "r"(a));
}
DEVI void ldm4t(uint32_t r[4], uint32_t a) {
    asm volatile("ldmatrix.sync.aligned.m8n8.x4.trans.shared.b16 {%0,%1,%2,%3}, [%4];"
                 : "=r"(r[0]), "=r"(r[1]), "=r"(r[2]), "=r"(r[3]) : "r"(a));
}
DEVI void mma16816(float c[4], const uint32_t a[4], uint32_t b0, uint32_t b1) {
    asm volatile(
        "mma.sync.aligned.m16n8k16.row.col.f32.bf16.bf16.f32 "
        "{%0,%1,%2,%3}, {%4,%5,%6,%7}, {%8,%9}, {%0,%1,%2,%3};"
        : "+f"(c[0]), "+f"(c[1]), "+f"(c[2]), "+f"(c[3])
        : "r"(a[0]), "r"(a[1]), "r"(a[2]), "r"(a[3]), "r"(b0), "r"(b1));
}
DEVI void cpa16(uint32_t s, const void* g) {
    asm volatile("cp.async.cg.shared.global [%0], [%1], 16;" :: "r"(s), "l"(g));
}
DEVI void cpa_commit() { asm volatile("cp.async.commit_group;"); }
template<int N> DEVI void cpa_wait() { asm volatile("cp.async.wait_group %0;" :: "n"(N)); }

// guaranteed MUFU.EX2
DEVI float ex2(float x) {
    float r;
    asm("ex2.approx.ftz.f32 %0, %1;" : "=f"(r) : "f"(x));
    return r;
}

DEVI uint32_t pack2(__nv_bfloat16 a, __nv_bfloat16 b) {
    __nv_bfloat162 t = __halves2bfloat162(a, b);
    return reinterpret_cast<uint32_t&>(t);
}
DEVI void split2(float a, float b, uint32_t& hi, uint32_t& lo) {
    __nv_bfloat16 ha = __float2bfloat16(a);
    __nv_bfloat16 hb = __float2bfloat16(b);
    hi = pack2(ha, hb);
    lo = pack2(__float2bfloat16(a - __bfloat162float(ha)),
               __float2bfloat16(b - __bfloat162float(hb)));
}

// ---------------- conversion kernels ------------------------------------------
__global__ __launch_bounds__(256) void conv_x_kernel(const float* __restrict__ x) {
    int i = blockIdx.x * 256 + threadIdx.x;
    float4 v = reinterpret_cast<const float4*>(x)[i];
    uint32_t h0, l0, h1, l1;
    split2(v.x, v.y, h0, l0);
    split2(v.z, v.w, h1, l1);
    reinterpret_cast<uint2*>(g_xhi)[i] = make_uint2(h0, h1);
    reinterpret_cast<uint2*>(g_xlo)[i] = make_uint2(l0, l1);
}

__global__ __launch_bounds__(256) void conv_w_kernel(
    const float* __restrict__ Wq, const float* __restrict__ Wk, const float* __restrict__ Wv) {
    if (blockIdx.x == 0 && blockIdx.y == 0 && threadIdx.x == 0)
        g_qkv_ctr = QKV_GRID;    // reset work-stealing counter (stream-ordered)
    int sel = blockIdx.y;
    const float* W = (sel == 0) ? Wq : (sel == 1 ? Wk : Wv);
    int i = blockIdx.x * 256 + threadIdx.x;
    float4 v = reinterpret_cast<const float4*>(W)[i];
    uint32_t h0, l0, h1, l1;
    split2(v.x, v.y, h0, l0);
    split2(v.z, v.w, h1, l1);
    reinterpret_cast<uint2*>(g_whi)[sel * 32768 + i] = make_uint2(h0, h1);
    reinterpret_cast<uint2*>(g_wlo)[sel * 32768 + i] = make_uint2(l0, l1);
}

// ---------------- kernel 1: QKV GEMM (BM=64, 128 thr, persistent + stealing) ----
namespace qk {
constexpr int A_HI = 0;          // 64 rows * 80B = 5120
constexpr int A_LO = 5120;
constexpr int B_HI = 10240;      // 32 rows * 272B = 8704
constexpr int B_LO = 18944;
constexpr int STG  = 27648;
constexpr int NEXT = STG * 2;    // 4-byte broadcast slot for stolen tile id
constexpr int SMEM = STG * 2 + 16;
}

__global__ __launch_bounds__(128) void qkv_kernel() {
    extern __shared__ char dsm[];
    const uint32_t sb0 = su32(dsm);

    const int tid  = threadIdx.x;
    const int warp = tid >> 5;
    const int lane = tid & 31;
    const int wm = warp & 1;
    const int wn = warp >> 1;
    const int g  = lane >> 2;
    const int tg = lane & 3;

    int u = blockIdx.x;   // tile id: sel = u>>8, m-tile = u&255

    while (u < QKV_TILES) {
        const int sel = u >> 8;
        const int m0  = (u & 255) * 64;
        __nv_bfloat16* Ohi = (sel == 0) ? g_qhi : (sel == 1 ? g_khi : g_vhi);
        __nv_bfloat16* Olo = (sel == 0) ? g_qlo : (sel == 1 ? g_klo : g_vlo);

        auto load_stage = [&](int st, int k0) {
            uint32_t sb = sb0 + st * qk::STG;
            // A: 64 rows x 64B (hi and lo), 16B chunks; row stride 80B (16-aligned).
            // 256 chunks each -> 2 iterations x 128 threads. (was 4 iters of cpa8)
#pragma unroll
            for (int i = 0; i < 2; i++) {
                int idx = tid + i * 128;          // 0..255
                int r = idx >> 2, c = idx & 3;
                uint32_t so = r * 80 + c * 16;
                size_t ge = (size_t)(m0 + r) * Cc + k0 + c * 8;
                cpa16(sb + qk::A_HI + so, (const char*)g_xhi + ge * 2);
                cpa16(sb + qk::A_LO + so, (const char*)g_xlo + ge * 2);
            }
            // B: 32 rows x 256B (hi and lo), 16B chunks; row stride 272B.
#pragma unroll
            for (int i = 0; i < 4; i++) {
                int idx = tid + i * 128;          // 0..511
                int r = idx >> 4, c = idx & 15;
                uint32_t so = r * 272 + c * 16;
                size_t ge = (size_t)sel * Cc * Dd + (size_t)(k0 + r) * Dd + c * 8;
                cpa16(sb + qk::B_HI + so, (const char*)g_whi + ge * 2);
                cpa16(sb + qk::B_LO + so, (const char*)g_wlo + ge * 2);
            }
            cpa_commit();
        };

        constexpr int NT = Cc / 32;
        load_stage(0, 0);
        load_stage(1, 32);

        float acc[2][8][4] = {};

        for (int t = 0; t < NT; t++) {
            if (t + 1 < NT) cpa_wait<1>(); else cpa_wait<0>();
            __syncthreads();

            uint32_t sb = sb0 + (t & 1) * qk::STG;
#pragma unroll
            for (int ks = 0; ks < 2; ks++) {
                uint32_t ah[2][4], al[2][4];
#pragma unroll
                for (int mi = 0; mi < 2; mi++) {
                    int arow = wm * 32 + mi * 16 + (lane & 15);
                    int acol = ks * 16 + (lane >> 4) * 8;
                    ldm4(ah[mi], sb + qk::A_HI + arow * 80 + acol * 2);
                    ldm4(al[mi], sb + qk::A_LO + arow * 80 + acol * 2);
                }
#pragma unroll
                for (int nb = 0; nb < 4; nb++) {
                    uint32_t bh[4], bl[4];
                    int brow = ks * 16 + (lane & 7) + ((lane >> 3) & 1) * 8;
                    int bcol = wn * 64 + nb * 16 + (lane >> 4) * 8;
                    ldm4t(bh, sb + qk::B_HI + brow * 272 + bcol * 2);
                    ldm4t(bl, sb + qk::B_LO + brow * 272 + bcol * 2);
#pragma unroll
                    for (int sub = 0; sub < 2; sub++) {
#pragma unroll
                        for (int mi = 0; mi < 2; mi++) {
                            float* cc = acc[mi][nb * 2 + sub];
                            mma16816(cc, ah[mi], bh[2 * sub], bh[2 * sub + 1]);
                            mma16816(cc, ah[mi], bl[2 * sub], bl[2 * sub + 1]);
                            mma16816(cc, al[mi], bh[2 * sub], bh[2 * sub + 1]);
                        }
                    }
                }
            }
            __syncthreads();
            if (t + 2 < NT) load_stage(t & 1, (t + 2) * 32);
        }

        const float sc = (sel == 0) ? SCALE_L2E : 1.0f;
#pragma unroll
        for (int mi = 0; mi < 2; mi++) {
            int r0 = m0 + wm * 32 + mi * 16 + g;
#pragma unroll
            for (int nj = 0; nj < 8; nj++) {
                int col = wn * 64 + nj * 8 + 2 * tg;
                uint32_t hi, lo;
                split2(acc[mi][nj][0] * sc, acc[mi][nj][1] * sc, hi, lo);
                *reinterpret_cast<uint32_t*>(&Ohi[(size_t)r0 * Dd + col]) = hi;
                *reinterpret_cast<uint32_t*>(&Olo[(size_t)r0 * Dd + col]) = lo;
                split2(acc[mi][nj][2] * sc, acc[mi][nj][3] * sc, hi, lo);
                *reinterpret_cast<uint32_t*>(&Ohi[(size_t)(r0 + 8) * Dd + col]) = hi;
                *reinterpret_cast<uint32_t*>(&Olo[(size_t)(r0 + 8) * Dd + col]) = lo;
            }
        }

        if (tid == 0) {
            unsigned int nx = atomicAdd(&g_qkv_ctr, 1u);
            *reinterpret_cast<uint32_t*>(dsm + qk::NEXT) = nx;
        }
        __syncthreads();
        u = (int)*reinterpret_cast<uint32_t*>(dsm + qk::NEXT);
    }
}

// ---------------- kernel 2: split-KV causal attention (round-13 champion) ------
namespace at {
constexpr int K_HI = 0;          // 32 rows * 272B = 8704 each
constexpr int K_LO = 8704;
constexpr int V_HI = 17408;
constexpr int V_LO = 26112;
constexpr int STG  = 34816;
constexpr int SMEM = STG * 2;    // 69632
}

__global__ __launch_bounds__(128) void attn_kernel()
{
    extern __shared__ char dsm[];
    const uint32_t sb0 = su32(dsm);

    // longest-first over CHUNK=512 chunks (round-13 while-loop mapping;
    // the (128,3) reg cap regressed in round 15 — 2 fat CTAs/SM beat 3 lean).
    int c = CTAS_PER_B - 1 - blockIdx.x;
    int grp = 0;
    while (4 * (grp + 1) * (grp + 2) <= c) grp++;
    int idx = c - 4 * grp * (grp + 1);
    const int itile = grp * 8 + idx / (grp + 1);
    const int ch    = idx % (grp + 1);

    const int bidx  = blockIdx.y;
    const int q0    = itile * QT;
    const int s_beg = ch * CHUNK;
    const int q_end = q0 + QT;
    const int s_end = (s_beg + CHUNK < q_end) ? (s_beg + CHUNK) : q_end;
    const int nt    = (s_end - s_beg) >> 5;

    const int tid  = threadIdx.x;
    const int warp = tid >> 5;
    const int lane = tid & 31;
    const int g  = lane >> 2;
    const int tg = lane & 3;
    const int wq = warp * 16;

    auto load_tile = [&](int st, int s0) {
        uint32_t sb = sb0 + st * at::STG;
        size_t gbyte = ((size_t)bidx * Tt + s0) * Dd * 2;
        const char* kh = (const char*)g_khi + gbyte;
        const char* kl = (const char*)g_klo + gbyte;
        const char* vh = (const char*)g_vhi + gbyte;
        const char* vl = (const char*)g_vlo + gbyte;
#pragma unroll
        for (int i = 0; i < 4; i++) {
            int idx2 = tid + i * 128;
            int r = idx2 >> 4, cc = idx2 & 15;
            uint32_t so = r * 272 + cc * 16;
            size_t go = (size_t)idx2 * 16;
            cpa16(sb + at::K_HI + so, kh + go);
            cpa16(sb + at::K_LO + so, kl + go);
            cpa16(sb + at::V_HI + so, vh + go);
            cpa16(sb + at::V_LO + so, vl + go);
        }
        cpa_commit();
    };

    uint32_t qh[8][4], ql[8][4];
    {
        size_t bt = ((size_t)bidx * Tt + q0 + wq + g) * Dd;
#pragma unroll
        for (int kt = 0; kt < 8; kt++) {
            int c0 = kt * 16 + 2 * tg;
            qh[kt][0] = *reinterpret_cast<const uint32_t*>(&g_qhi[bt + c0]);
            qh[kt][1] = *reinterpret_cast<const uint32_t*>(&g_qhi[bt + 8 * Dd + c0]);
            qh[kt][2] = *reinterpret_cast<const uint32_t*>(&g_qhi[bt + c0 + 8]);
            qh[kt][3] = *reinterpret_cast<const uint32_t*>(&g_qhi[bt + 8 * Dd + c0 + 8]);
            ql[kt][0] = *reinterpret_cast<const uint32_t*>(&g_qlo[bt + c0]);
            ql[kt][1] = *reinterpret_cast<const uint32_t*>(&g_qlo[bt + 8 * Dd + c0]);
            ql[kt][2] = *reinterpret_cast<const uint32_t*>(&g_qlo[bt + c0 + 8]);
            ql[kt][3] = *reinterpret_cast<const uint32_t*>(&g_qlo[bt + 8 * Dd + c0 + 8]);
        }
    }

    float oacc[16][4] = {};
    float l_t = 0.f, l_b = 0.f;

    load_tile(0, s_beg);
    if (nt > 1) load_tile(1, s_beg + 32);

    for (int t = 0; t < nt; t++) {
        if (t + 1 < nt) cpa_wait<1>(); else cpa_wait<0>();
        __syncthreads();

        const uint32_t sb = sb0 + (t & 1) * at::STG;
        const int s0 = s_beg + t * 32;

        float sacc[4][4] = {};
#pragma unroll
        for (int kt = 0; kt < 8; kt++) {
#pragma unroll
            for (int np = 0; np < 2; np++) {
                uint32_t kh[4], kl[4];
                int srow = np * 16 + ((lane >> 4) << 3) + (lane & 7);
                int kcol = kt * 16 + ((lane >> 3) & 1) * 8;
                ldm4(kh, sb + at::K_HI + srow * 272 + kcol * 2);
                ldm4(kl, sb + at::K_LO + srow * 272 + kcol * 2);
#pragma unroll
                for (int sub = 0; sub < 2; sub++) {
                    float* cc = sacc[np * 2 + sub];
                    mma16816(cc, qh[kt], kh[2 * sub], kh[2 * sub + 1]);
                    mma16816(cc, qh[kt], kl[2 * sub], kl[2 * sub + 1]);
                    mma16816(cc, ql[kt], kh[2 * sub], kh[2 * sub + 1]);
                }
            }
        }

        const int rt = q0 + wq + g;
        if (s0 + 31 > q0 + wq) {
#pragma unroll
            for (int nj = 0; nj < 4; nj++) {
                int cgl = s0 + nj * 8 + 2 * tg;
                if (cgl     > rt)     sacc[nj][0] = -1e30f;
                if (cgl + 1 > rt)     sacc[nj][1] = -1e30f;
                if (cgl     > rt + 8) sacc[nj][2] = -1e30f;
                if (cgl + 1 > rt + 8) sacc[nj][3] = -1e30f;
            }
        }

        // fixed-base softmax: P = 2^S (masked -> 0); accumulate l per thread
#pragma unroll
        for (int nj = 0; nj < 4; nj++) {
            sacc[nj][0] = ex2(sacc[nj][0]);
            sacc[nj][1] = ex2(sacc[nj][1]);
            sacc[nj][2] = ex2(sacc[nj][2]);
            sacc[nj][3] = ex2(sacc[nj][3]);
            l_t += sacc[nj][0] + sacc[nj][1];
            l_b += sacc[nj][2] + sacc[nj][3];
        }

        uint32_t ph[2][4], pl[2][4];
#pragma unroll
        for (int kb = 0; kb < 2; kb++) {
            split2(sacc[kb * 2][0],     sacc[kb * 2][1],     ph[kb][0], pl[kb][0]);
            split2(sacc[kb * 2][2],     sacc[kb * 2][3],     ph[kb][1], pl[kb][1]);
            split2(sacc[kb * 2 + 1][0], sacc[kb * 2 + 1][1], ph[kb][2], pl[kb][2]);
            split2(sacc[kb * 2 + 1][2], sacc[kb * 2 + 1][3], ph[kb][3], pl[kb][3]);
        }
#pragma unroll
        for (int kb = 0; kb < 2; kb++) {
            int vrow = kb * 16 + (lane & 7) + ((lane >> 3) & 1) * 8;
#pragma unroll
            for (int db = 0; db < 8; db++) {
                uint32_t vh[4], vl[4];
                int vcol = db * 16 + (lane >> 4) * 8;
                ldm4t(vh, sb + at::V_HI + vrow * 272 + vcol * 2);
                ldm4t(vl, sb + at::V_LO + vrow * 272 + vcol * 2);
#pragma unroll
                for (int sub = 0; sub < 2; sub++) {
                    float* cc = oacc[db * 2 + sub];
                    mma16816(cc, ph[kb], vh[2 * sub], vh[2 * sub + 1]);
                    mma16816(cc, pl[kb], vh[2 * sub], vh[2 * sub + 1]);
                    mma16816(cc, ph[kb], vl[2 * sub], vl[2 * sub + 1]);
                }
            }
        }

        __syncthreads();
        if (t + 2 < nt) load_tile(t & 1, s_beg + (t + 2) * 32);
    }

    l_t += __shfl_xor_sync(0xffffffffu, l_t, 1);
    l_t += __shfl_xor_sync(0xffffffffu, l_t, 2);
    l_b += __shfl_xor_sync(0xffffffffu, l_b, 1);
    l_b += __shfl_xor_sync(0xffffffffu, l_b, 2);

    const int part  = ((bidx * NQT + itile) * MAXCH + ch);
    const int row_t = wq + g;
    float* po = &g_po[(size_t)part * QT * Dd];
    if (tg == 0) {
        g_pl[part * QT + row_t]     = l_t;
        g_pl[part * QT + row_t + 8] = l_b;
    }
#pragma unroll
    for (int d = 0; d < 16; d++) {
        int col = d * 8 + 2 * tg;
        *reinterpret_cast<float2*>(&po[row_t * Dd + col])       = make_float2(oacc[d][0], oacc[d][1]);
        *reinterpret_cast<float2*>(&po[(row_t + 8) * Dd + col]) = make_float2(oacc[d][2], oacc[d][3]);
    }
}

// ---------------- kernel 3: combine (plain sum; shared base) --------------------
__global__ __launch_bounds__(128) void combine_kernel(float* __restrict__ out)
{
    const int warp = threadIdx.x >> 5;
    const int lane = threadIdx.x & 31;
    const int r = blockIdx.x * 4 + warp;
    const int b = r >> 12;
    const int rem = r & 4095;
    const int i = rem >> 6;
    const int row_in = rem & 63;
    const int nch = (i >> 3) + 1;     // CHUNK=512: group = i>>3

    const int pbase = ((b * NQT + i) * MAXCH);

    float4 acc = make_float4(0.f, 0.f, 0.f, 0.f);
    float lsum = 0.f;
#pragma unroll
    for (int cch = 0; cch < MAXCH; cch++) {
        if (cch >= nch) break;
        lsum += g_pl[(pbase + cch) * QT + row_in];
        float4 v = *reinterpret_cast<const float4*>(
            &g_po[((size_t)(pbase + cch) * QT + row_in) * Dd + lane * 4]);
        acc.x += v.x; acc.y += v.y; acc.z += v.z; acc.w += v.w;
    }
    float inv = 1.f / lsum;
    float4 o = make_float4(acc.x * inv, acc.y * inv, acc.z * inv, acc.w * inv);
    *reinterpret_cast<float4*>(&out[((size_t)b * Tt + i * QT + row_in) * Dd + lane * 4]) = o;
}

// ---------------- launcher --------------------------------------------------------
extern "C" void kernel_launch(void* const* d_in, const int* in_sizes, int n_in,
                              void* d_out, int out_size) {
    const float* x  = (const float*)d_in[0];
    const float* Wq = (const float*)d_in[1];
    const float* Wk = (const float*)d_in[2];
    const float* Wv = (const float*)d_in[3];
    float* out = (float*)d_out;

    cudaFuncSetAttribute(qkv_kernel, cudaFuncAttributeMaxDynamicSharedMemorySize, qk::SMEM);
    cudaFuncSetAttribute(attn_kernel, cudaFuncAttributeMaxDynamicSharedMemorySize, at::SMEM);

    conv_x_kernel<<<(Mm * Cc / 4) / 256, 256>>>(x);
    conv_w_kernel<<<dim3((Cc * Dd / 4) / 256, 3), 256>>>(Wq, Wk, Wv);
    qkv_kernel<<<QKV_GRID, 128, qk::SMEM>>>();
    attn_kernel<<<dim3(CTAS_PER_B, Bb), 128, at::SMEM>>>();
    combine_kernel<<<Mm / 4, 128>>>(out);
}